// round 4
// baseline (speedup 1.0000x reference)
#include <cuda_runtime.h>
#include <cstddef>

// Problem constants (shapes are fixed for this problem instance)
#define NN   32768   // nodes
#define EE   16384   // hyperedges
#define DDN  4       // edges per node
#define KKN  8       // nodes per edge
#define HID  128     // IN_DIM == OUT_DIM
#define EDIM 64      // EDGE_DIM
#define NHD  8       // heads
#define LLK  32      // keys per node = DDN*KKN

// -------------------- scratch (device globals; no allocations) --------------
__device__ float g_Wc[3 * 128 * 128];   // combined Wq*Wlin, Wk*Wlin, Wv*Wlin
__device__ float g_We[128 * 64];        // combined Wk*W_edge
__device__ float g_Q[(size_t)NN * 128];
__device__ float g_KWh[(size_t)NN * 128];
__device__ float g_VWh[(size_t)NN * 128];
__device__ float g_KWe[(size_t)EE * 128];
__device__ float g_CTX[(size_t)NN * 128];

// -------------------- K0: weight folding ------------------------------------
// g_Wc[mat][o][i] = sum_j Wt[o,j] * W_lin[j,i]   (mat: 0=Wq,1=Wk,2=Wv)
// g_We[o][i]      = sum_j Wk[o,j] * W_edge[j,i]
__global__ void combine_w(const float* __restrict__ Wlin,
                          const float* __restrict__ Wedge,
                          const float* __restrict__ Wq,
                          const float* __restrict__ Wk,
                          const float* __restrict__ Wv)
{
    int o   = blockIdx.x;      // 0..127 output row
    int mat = blockIdx.y;      // 0..3
    int i   = threadIdx.x;     // 0..127 input col

    if (mat < 3) {
        const float* Wt = (mat == 0) ? Wq : ((mat == 1) ? Wk : Wv);
        float s = 0.f;
        #pragma unroll 8
        for (int j = 0; j < 128; j++)
            s = fmaf(Wt[o * 128 + j], Wlin[j * 128 + i], s);
        g_Wc[((size_t)mat * 128 + o) * 128 + i] = s;
    } else {
        if (i < 64) {
            float s = 0.f;
            #pragma unroll 8
            for (int j = 0; j < 128; j++)
                s = fmaf(Wk[o * 128 + j], Wedge[j * 64 + i], s);
            g_We[o * 64 + i] = s;
        }
    }
}

// -------------------- tiled fp32 NT-GEMM ------------------------------------
// C[M,128] = act(A[M,Ka] @ B[128,Ka]^T + bias)
// BM=128, BN=128(full), BK=16; 256 threads; 8x8 per thread.
__global__ void __launch_bounds__(256)
gemm_nt_128(const float* __restrict__ A, const float* __restrict__ B,
            const float* __restrict__ bias, float* __restrict__ C,
            int M, int Ka, int doRelu)
{
    __shared__ float As[16][132];
    __shared__ float Bs[16][132];

    const int tid = threadIdx.x;
    const int bm  = blockIdx.x * 128;
    const int tx  = tid & 15;     // col group
    const int ty  = tid >> 4;     // row group

    float acc[8][8];
    #pragma unroll
    for (int i = 0; i < 8; i++)
        #pragma unroll
        for (int j = 0; j < 8; j++) acc[i][j] = 0.f;

    for (int k0 = 0; k0 < Ka; k0 += 16) {
        // cooperative loads: 512 float4 for A-tile, 512 for B-tile
        #pragma unroll
        for (int it = 0; it < 2; it++) {
            int idx = tid * 2 + it;       // 0..511
            int m   = idx >> 2;           // row in tile (0..127)
            int kq  = (idx & 3) * 4;      // k offset in tile
            float4 a = *(const float4*)(A + (size_t)(bm + m) * Ka + (k0 + kq));
            As[kq + 0][m] = a.x; As[kq + 1][m] = a.y;
            As[kq + 2][m] = a.z; As[kq + 3][m] = a.w;
            float4 b = *(const float4*)(B + (size_t)m * Ka + (k0 + kq));
            Bs[kq + 0][m] = b.x; Bs[kq + 1][m] = b.y;
            Bs[kq + 2][m] = b.z; Bs[kq + 3][m] = b.w;
        }
        __syncthreads();

        #pragma unroll
        for (int kk = 0; kk < 16; kk++) {
            float ar[8], br[8];
            #pragma unroll
            for (int i = 0; i < 8; i++) ar[i] = As[kk][ty * 8 + i];
            #pragma unroll
            for (int j = 0; j < 8; j++) br[j] = Bs[kk][tx * 8 + j];
            #pragma unroll
            for (int i = 0; i < 8; i++)
                #pragma unroll
                for (int j = 0; j < 8; j++)
                    acc[i][j] = fmaf(ar[i], br[j], acc[i][j]);
        }
        __syncthreads();
    }

    float bcol[8];
    #pragma unroll
    for (int j = 0; j < 8; j++) bcol[j] = bias ? bias[tx * 8 + j] : 0.f;

    #pragma unroll
    for (int i = 0; i < 8; i++) {
        int row = bm + ty * 8 + i;
        #pragma unroll
        for (int jj = 0; jj < 8; jj += 4) {
            float4 c;
            c.x = acc[i][jj + 0] + bcol[jj + 0];
            c.y = acc[i][jj + 1] + bcol[jj + 1];
            c.z = acc[i][jj + 2] + bcol[jj + 2];
            c.w = acc[i][jj + 3] + bcol[jj + 3];
            if (doRelu) {
                c.x = fmaxf(c.x, 0.f); c.y = fmaxf(c.y, 0.f);
                c.z = fmaxf(c.z, 0.f); c.w = fmaxf(c.w, 0.f);
            }
            *(float4*)(C + (size_t)row * 128 + tx * 8 + jj) = c;
        }
    }
}

// -------------------- attention: one warp per node ---------------------------
// score[n,h,l] = (q[n,h,:].KWh[u_l,h,:] + q[n,h,:].KWe[e_{l/8},h,:]) / 4
// ctx[n,h,:]   = sum_l softmax_l(score) * VWh[u_l,h,:]
__global__ void __launch_bounds__(256)
attn_kernel(const int* __restrict__ node_edges,
            const int* __restrict__ edge_nodes)
{
    __shared__ float sc[8][8][32];       // [warp][head][l]

    const unsigned FULL = 0xffffffffu;
    int t = threadIdx.x & 31;            // lane
    int w = threadIdx.x >> 5;            // warp in block
    int n = blockIdx.x * 8 + w;          // node

    int d = t >> 3, j = t & 7;
    int e = node_edges[n * DDN + d];     // lane's edge (for l = t)
    int u = edge_nodes[e * KKN + j];     // lane's neighbor node (for l = t)

    float4 q = ((const float4*)(g_Q + (size_t)n * 128))[t];  // dims [4t,4t+3]
    int g = t >> 2;                      // head of this lane's dims

    // edge term, once per edge (reused by 8 keys)
    float es[4];
    #pragma unroll
    for (int dd = 0; dd < 4; dd++) {
        int ee = __shfl_sync(FULL, e, dd * 8);
        float4 kf = ((const float4*)(g_KWe + (size_t)ee * 128))[t];
        float p = fmaf(q.x, kf.x, fmaf(q.y, kf.y, fmaf(q.z, kf.z, q.w * kf.w)));
        p += __shfl_xor_sync(FULL, p, 1);
        p += __shfl_xor_sync(FULL, p, 2);
        es[dd] = p;
    }

    // node-key term
    #pragma unroll
    for (int l = 0; l < 32; l++) {
        int uu = __shfl_sync(FULL, u, l);
        float4 kf = ((const float4*)(g_KWh + (size_t)uu * 128))[t];
        float p = fmaf(q.x, kf.x, fmaf(q.y, kf.y, fmaf(q.z, kf.z, q.w * kf.w)));
        p += __shfl_xor_sync(FULL, p, 1);
        p += __shfl_xor_sync(FULL, p, 2);
        if ((t & 3) == 0) sc[w][g][l] = (p + es[l >> 3]) * 0.25f;  // /sqrt(16)
    }
    __syncwarp();

    // per-head softmax over 32 keys; 4-lane group g owns head g
    {
        int r = t & 3;
        float vv[8];
        float m = -1e30f;
        #pragma unroll
        for (int i = 0; i < 8; i++) { vv[i] = sc[w][g][r + i * 4]; m = fmaxf(m, vv[i]); }
        m = fmaxf(m, __shfl_xor_sync(FULL, m, 1));
        m = fmaxf(m, __shfl_xor_sync(FULL, m, 2));
        float s = 0.f;
        #pragma unroll
        for (int i = 0; i < 8; i++) { vv[i] = __expf(vv[i] - m); s += vv[i]; }
        s += __shfl_xor_sync(FULL, s, 1);
        s += __shfl_xor_sync(FULL, s, 2);
        float inv = 1.0f / s;
        #pragma unroll
        for (int i = 0; i < 8; i++) sc[w][g][r + i * 4] = vv[i] * inv;
    }
    __syncwarp();

    // context
    float4 acc = make_float4(0.f, 0.f, 0.f, 0.f);
    #pragma unroll
    for (int l = 0; l < 32; l++) {
        int uu = __shfl_sync(FULL, u, l);
        float a = sc[w][g][l];
        float4 vf = ((const float4*)(g_VWh + (size_t)uu * 128))[t];
        acc.x = fmaf(a, vf.x, acc.x);
        acc.y = fmaf(a, vf.y, acc.y);
        acc.z = fmaf(a, vf.z, acc.z);
        acc.w = fmaf(a, vf.w, acc.w);
    }
    ((float4*)(g_CTX + (size_t)n * 128))[t] = acc;
}

// -------------------- launch -------------------------------------------------
extern "C" void kernel_launch(void* const* d_in, const int* in_sizes, int n_in,
                              void* d_out, int out_size)
{
    const float* x          = (const float*)d_in[0];
    const float* edge_attr  = (const float*)d_in[1];
    const int*   node_edges = (const int*)  d_in[2];
    const int*   edge_nodes = (const int*)  d_in[3];
    const float* W_lin      = (const float*)d_in[4];
    const float* W_edge     = (const float*)d_in[5];
    const float* Wq         = (const float*)d_in[6];
    const float* Wk         = (const float*)d_in[7];
    const float* Wv         = (const float*)d_in[8];
    const float* bq         = (const float*)d_in[9];
    const float* bk         = (const float*)d_in[10];
    const float* bv         = (const float*)d_in[11];
    const float* Wo         = (const float*)d_in[12];
    const float* bo         = (const float*)d_in[13];
    float*       out        = (float*)d_out;

    int Nn = in_sizes[0] / HID;    // 32768
    int En = in_sizes[1] / EDIM;   // 16384

    float *pWc, *pWe, *pQ, *pKWh, *pVWh, *pKWe, *pCTX;
    cudaGetSymbolAddress((void**)&pWc,  g_Wc);
    cudaGetSymbolAddress((void**)&pWe,  g_We);
    cudaGetSymbolAddress((void**)&pQ,   g_Q);
    cudaGetSymbolAddress((void**)&pKWh, g_KWh);
    cudaGetSymbolAddress((void**)&pVWh, g_VWh);
    cudaGetSymbolAddress((void**)&pKWe, g_KWe);
    cudaGetSymbolAddress((void**)&pCTX, g_CTX);

    // K0: fold weights
    combine_w<<<dim3(128, 4), 128>>>(W_lin, W_edge, Wq, Wk, Wv);

    // K1: node projections  Q = x*(Wq Wlin)^T + bq ; KWh = x*(Wk Wlin)^T ; VWh = x*(Wv Wlin)^T + bv
    gemm_nt_128<<<Nn / 128, 256>>>(x, pWc,               bq,      pQ,   Nn, 128, 0);
    gemm_nt_128<<<Nn / 128, 256>>>(x, pWc + 128 * 128,   nullptr, pKWh, Nn, 128, 0);
    gemm_nt_128<<<Nn / 128, 256>>>(x, pWc + 2 * 128 * 128, bv,    pVWh, Nn, 128, 0);

    // K2: edge projection  KWe = edge_attr*(Wk W_edge)^T + bk
    gemm_nt_128<<<En / 128, 256>>>(edge_attr, pWe, bk, pKWe, En, 64, 0);

    // K3: attention -> ctx
    attn_kernel<<<Nn / 8, 256>>>(node_edges, edge_nodes);

    // K4: out = relu(ctx * Wo^T + bo)
    gemm_nt_128<<<Nn / 128, 256>>>(pCTX, Wo, bo, out, Nn, 128, 1);
}